// round 4
// baseline (speedup 1.0000x reference)
#include <cuda_runtime.h>
#include <cstdint>
#include <cstring>

#define T_STEPS 2048
#define BATCH   8
#define DIMK    1024
#define NST     64
#define M_ROWS  (T_STEPS * BATCH)
#define NCOL    256

// 16 MB scratch: projections, layout [t*BATCH+b][ k(0:64) | q(64:128) | v(128:192) | alpha(192:256) ]
__device__ __align__(16) float g_proj[(size_t)M_ROWS * NCOL];

union F2U { float2 f2; unsigned long long u; };

__device__ __forceinline__ float2 f2fma(float2 a, float2 b, float2 c) {
    F2U ua, ub, uc, ud; ua.f2 = a; ub.f2 = b; uc.f2 = c;
    asm("fma.rn.f32x2 %0, %1, %2, %3;" : "=l"(ud.u) : "l"(ua.u), "l"(ub.u), "l"(uc.u));
    return ud.f2;
}
__device__ __forceinline__ float2 f2mul(float2 a, float2 b) {
    F2U ua, ub, ud; ua.f2 = a; ub.f2 = b;
    asm("mul.rn.f32x2 %0, %1, %2;" : "=l"(ud.u) : "l"(ua.u), "l"(ub.u));
    return ud.f2;
}
__device__ __forceinline__ float2 f2add(float2 a, float2 b) {
    F2U ua, ub, ud; ua.f2 = a; ub.f2 = b;
    asm("add.rn.f32x2 %0, %1, %2;" : "=l"(ud.u) : "l"(ua.u), "l"(ub.u));
    return ud.f2;
}
__device__ __forceinline__ float2 f2dup(float a) {
    F2U ud;
    asm("mov.b64 %0, {%1, %1};" : "=l"(ud.u) : "f"(a));
    return ud.f2;
}
__device__ __forceinline__ float sigmoidf_fast(float x) {
    return __fdividef(1.0f, 1.0f + __expf(-x));
}

// ============================================================================
// Kernel 1: fused projection GEMM, 8x8 microtile, two weight matrices/block.
//   blockIdx.y == 0: B rows = [Wk(64) | Wq(64)] -> g_proj cols 0..127
//   blockIdx.y == 1: B rows = [Wv(64) | Wa(64)] -> g_proj cols 128..255
// C[m][n] = sum_d x[m][d] * W[n][d].  BM=128, BN=128, BK=16, 256 threads.
// ============================================================================
#define PBM 128
#define PBN 128
#define PBK 16

__global__ void __launch_bounds__(256) proj_kernel(
    const float* __restrict__ x,
    const float* __restrict__ Wk, const float* __restrict__ Wq,
    const float* __restrict__ Wv, const float* __restrict__ Wa,
    const float* __restrict__ b_alpha)
{
    __shared__ __align__(16) float As[PBK][PBM + 4];
    __shared__ __align__(16) float Bs[PBK][PBN + 4];

    const int tid = threadIdx.x;
    const int m0  = blockIdx.x * PBM;
    const int y   = blockIdx.y;
    const float* Wlo = y ? Wv : Wk;
    const float* Whi = y ? Wa : Wq;

    // loader indices: each thread loads 8 consecutive floats of one row
    const int lrow = tid >> 1;        // 0..127
    const int lcol = (tid & 1) * 8;   // 0 or 8

    // compute indices: 8 rows x 8 cols per thread
    const int ty = tid >> 4;          // 0..15 -> rows ty*8..+7
    const int tx = tid & 15;          // 0..15 -> cols tx*8..+7

    const float* xp = &x[(size_t)(m0 + lrow) * DIMK + lcol];
    const float* wp = (lrow < 64) ? &Wlo[(size_t)lrow * DIMK + lcol]
                                  : &Whi[(size_t)(lrow - 64) * DIMK + lcol];

    float2 acc[4][8];
    #pragma unroll
    for (int ip = 0; ip < 4; ip++)
        #pragma unroll
        for (int j = 0; j < 8; j++) acc[ip][j] = make_float2(0.f, 0.f);

    // register prefetch of first K-tile
    float4 xa = *reinterpret_cast<const float4*>(xp);
    float4 xb = *reinterpret_cast<const float4*>(xp + 4);
    float4 wa = *reinterpret_cast<const float4*>(wp);
    float4 wb = *reinterpret_cast<const float4*>(wp + 4);

    for (int k0 = 0; k0 < DIMK; k0 += PBK) {
        __syncthreads();
        // store transposed: As[k][m], Bs[k][n]
        As[lcol + 0][lrow] = xa.x; As[lcol + 1][lrow] = xa.y;
        As[lcol + 2][lrow] = xa.z; As[lcol + 3][lrow] = xa.w;
        As[lcol + 4][lrow] = xb.x; As[lcol + 5][lrow] = xb.y;
        As[lcol + 6][lrow] = xb.z; As[lcol + 7][lrow] = xb.w;
        Bs[lcol + 0][lrow] = wa.x; Bs[lcol + 1][lrow] = wa.y;
        Bs[lcol + 2][lrow] = wa.z; Bs[lcol + 3][lrow] = wa.w;
        Bs[lcol + 4][lrow] = wb.x; Bs[lcol + 5][lrow] = wb.y;
        Bs[lcol + 6][lrow] = wb.z; Bs[lcol + 7][lrow] = wb.w;
        __syncthreads();

        // prefetch next K-tile while computing this one
        if (k0 + PBK < DIMK) {
            xa = *reinterpret_cast<const float4*>(xp + k0 + PBK);
            xb = *reinterpret_cast<const float4*>(xp + k0 + PBK + 4);
            wa = *reinterpret_cast<const float4*>(wp + k0 + PBK);
            wb = *reinterpret_cast<const float4*>(wp + k0 + PBK + 4);
        }

        #pragma unroll
        for (int k = 0; k < PBK; k++) {
            float4 a0 = *reinterpret_cast<const float4*>(&As[k][ty * 8]);
            float4 a1 = *reinterpret_cast<const float4*>(&As[k][ty * 8 + 4]);
            float4 b0 = *reinterpret_cast<const float4*>(&Bs[k][tx * 8]);
            float4 b1 = *reinterpret_cast<const float4*>(&Bs[k][tx * 8 + 4]);
            float2 am[4] = { make_float2(a0.x, a0.y), make_float2(a0.z, a0.w),
                             make_float2(a1.x, a1.y), make_float2(a1.z, a1.w) };
            float2 bd[8] = { f2dup(b0.x), f2dup(b0.y), f2dup(b0.z), f2dup(b0.w),
                             f2dup(b1.x), f2dup(b1.y), f2dup(b1.z), f2dup(b1.w) };
            #pragma unroll
            for (int ip = 0; ip < 4; ip++)
                #pragma unroll
                for (int j = 0; j < 8; j++)
                    acc[ip][j] = f2fma(am[ip], bd[j], acc[ip][j]);
        }
    }

    // epilogue: rows m0 + ty*8 + 2*ip + h, cols y*128 + tx*8 + j
    const bool alpha_cols = (y == 1) && (tx >= 8);   // global cols >= 192
    #pragma unroll
    for (int ip = 0; ip < 4; ip++) {
        #pragma unroll
        for (int h = 0; h < 2; h++) {
            const int r = ty * 8 + ip * 2 + h;
            float o[8];
            #pragma unroll
            for (int j = 0; j < 8; j++)
                o[j] = h ? acc[ip][j].y : acc[ip][j].x;
            if (alpha_cols) {
                #pragma unroll
                for (int j = 0; j < 8; j++)
                    o[j] = sigmoidf_fast(o[j] + b_alpha[(tx - 8) * 8 + j]);
            }
            float* dst = &g_proj[(size_t)(m0 + r) * NCOL + y * 128 + tx * 8];
            *reinterpret_cast<float4*>(dst)     = make_float4(o[0], o[1], o[2], o[3]);
            *reinterpret_cast<float4*>(dst + 4) = make_float4(o[4], o[5], o[6], o[7]);
        }
    }
}

// ============================================================================
// Kernel 2: sequential scan (unchanged structure from R3) + fused self-gate.
// 128 blocks x 32 threads; 4 rows/warp, 8 lanes/row, 8 state elems/lane.
// Deferred output: out(t-1) = S_t . q_{t-1} at top of iter t.
// ============================================================================
#define DPF 8   // ring slots

__global__ void __launch_bounds__(32) scan_kernel(
    const float* __restrict__ S0,
    const float* __restrict__ d_g,
    const float* __restrict__ b_g,
    float* __restrict__ out,     // [T,B,N]  (gated values)
    float* __restrict__ Sfin)    // [B,N,N]
{
    __shared__ __align__(16) float buf[DPF][NCOL];

    const int bx   = blockIdx.x;
    const int b    = bx >> 4;          // batch 0..7
    const int rg   = bx & 15;          // row group 0..15
    const int lane = threadIdx.x;
    const int r    = lane >> 3;        // row within group 0..3
    const int c    = lane & 7;         // column slice 0..7 (8 elems each)
    const int i    = rg * 4 + r;       // global row 0..63

    const float L2E = 1.4426950408889634f;
    const float dgl = -d_g[i] * L2E;
    const float bgl = -b_g[i] * L2E;

    float2 s[4];
    {
        const float4* sp = reinterpret_cast<const float4*>(&S0[(size_t)(b * NST + i) * NST + c * 8]);
        float4 v0 = sp[0], v1 = sp[1];
        s[0] = make_float2(v0.x, v0.y); s[1] = make_float2(v0.z, v0.w);
        s[2] = make_float2(v1.x, v1.y); s[3] = make_float2(v1.z, v1.w);
    }

    const uint32_t sbase = (uint32_t)__cvta_generic_to_shared(&buf[0][0]);
    const int loff = lane * 8;   // floats

    #pragma unroll
    for (int d = 0; d < DPF - 1; d++) {
        const float* src = &g_proj[((size_t)d * BATCH + b) * NCOL + loff];
        uint32_t sa = sbase + (uint32_t)(d * NCOL + loff) * 4u;
        asm volatile(
            "cp.async.ca.shared.global [%0], [%1], 16;\n\t"
            "cp.async.ca.shared.global [%2], [%3], 16;\n\t"
            :: "r"(sa), "l"(src), "r"(sa + 16u), "l"(src + 4));
        asm volatile("cp.async.commit_group;");
    }
    asm volatile("cp.async.wait_group %0;" :: "n"(DPF - 2));
    __syncwarp();

    float2 kk[4], qq[4], qp[4];
    float v_i, a_i;
    {
        const float* p = &buf[0][0];
        float4 kv0 = *reinterpret_cast<const float4*>(p + c * 8);
        float4 kv1 = *reinterpret_cast<const float4*>(p + c * 8 + 4);
        float4 qv0 = *reinterpret_cast<const float4*>(p + 64 + c * 8);
        float4 qv1 = *reinterpret_cast<const float4*>(p + 64 + c * 8 + 4);
        kk[0] = make_float2(kv0.x, kv0.y); kk[1] = make_float2(kv0.z, kv0.w);
        kk[2] = make_float2(kv1.x, kv1.y); kk[3] = make_float2(kv1.z, kv1.w);
        qq[0] = make_float2(qv0.x, qv0.y); qq[1] = make_float2(qv0.z, qv0.w);
        qq[2] = make_float2(qv1.x, qv1.y); qq[3] = make_float2(qv1.z, qv1.w);
        v_i = p[128 + i];
        a_i = p[192 + i];
    }
    #pragma unroll
    for (int m = 0; m < 4; m++) qp[m] = make_float2(0.f, 0.f);

    for (int t = 0; t < T_STEPS; t++) {
        {
            int tf = t + DPF - 1;
            if (tf > T_STEPS - 1) tf = T_STEPS - 1;
            int slot = tf & (DPF - 1);
            const float* src = &g_proj[((size_t)tf * BATCH + b) * NCOL + loff];
            uint32_t sa = sbase + (uint32_t)(slot * NCOL + loff) * 4u;
            asm volatile(
                "cp.async.ca.shared.global [%0], [%1], 16;\n\t"
                "cp.async.ca.shared.global [%2], [%3], 16;\n\t"
                :: "r"(sa), "l"(src), "r"(sa + 16u), "l"(src + 4));
            asm volatile("cp.async.commit_group;");
        }
        asm volatile("cp.async.wait_group %0;" :: "n"(DPF - 2));
        __syncwarp();

        // register-prefetch step t+1 operands
        float2 kn[4], qn[4];
        float v_n, a_n;
        {
            int tn = (t + 1 < T_STEPS) ? (t + 1) : t;
            const float* p = &buf[tn & (DPF - 1)][0];
            float4 kv0 = *reinterpret_cast<const float4*>(p + c * 8);
            float4 kv1 = *reinterpret_cast<const float4*>(p + c * 8 + 4);
            float4 qv0 = *reinterpret_cast<const float4*>(p + 64 + c * 8);
            float4 qv1 = *reinterpret_cast<const float4*>(p + 64 + c * 8 + 4);
            kn[0] = make_float2(kv0.x, kv0.y); kn[1] = make_float2(kv0.z, kv0.w);
            kn[2] = make_float2(kv1.x, kv1.y); kn[3] = make_float2(kv1.z, kv1.w);
            qn[0] = make_float2(qv0.x, qv0.y); qn[1] = make_float2(qv0.z, qv0.w);
            qn[2] = make_float2(qv1.x, qv1.y); qn[3] = make_float2(qv1.z, qv1.w);
            v_n = p[128 + i];
            a_n = p[192 + i];
        }

        // two dots on s: rk = s.k_t (feeds sigmoid), oq = s.q_{t-1} = out(t-1)
        float2 ra = f2mul(s[0], kk[0]);
        float2 rb = f2mul(s[1], kk[1]);
        float2 oa = f2mul(s[0], qp[0]);
        float2 ob = f2mul(s[1], qp[1]);
        ra = f2fma(s[2], kk[2], ra);
        rb = f2fma(s[3], kk[3], rb);
        oa = f2fma(s[2], qp[2], oa);
        ob = f2fma(s[3], qp[3], ob);
        ra = f2add(ra, rb);
        oa = f2add(oa, ob);
        float rk = ra.x + ra.y;
        float oq = oa.x + oa.y;

        rk += __shfl_xor_sync(0xffffffffu, rk, 1);
        oq += __shfl_xor_sync(0xffffffffu, oq, 1);
        rk += __shfl_xor_sync(0xffffffffu, rk, 2);
        oq += __shfl_xor_sync(0xffffffffu, oq, 2);
        rk += __shfl_xor_sync(0xffffffffu, rk, 4);
        oq += __shfl_xor_sync(0xffffffffu, oq, 4);

        const float cvi = (1.0f - a_i) * v_i;

        // g = sigmoid(d*rk + b): FMA -> EX2 -> ADD -> RCP
        float e;
        asm("ex2.approx.f32 %0, %1;" : "=f"(e) : "f"(__fmaf_rn(dgl, rk, bgl)));
        float gt;
        asm("rcp.approx.f32 %0, %1;" : "=f"(gt) : "f"(1.0f + e));

        const float beta = cvi * gt;
        const float2 av = f2dup(a_i);
        const float2 bv = f2dup(beta);

        #pragma unroll
        for (int m = 0; m < 4; m++)
            s[m] = f2fma(av, s[m], f2mul(bv, kk[m]));

        // gated output out(t-1) = oq^2 * sigmoid(oq)   (off the carried path)
        if (t > 0 && c == 0) {
            float eg;
            asm("ex2.approx.f32 %0, %1;" : "=f"(eg) : "f"(-L2E * oq));
            float sg;
            asm("rcp.approx.f32 %0, %1;" : "=f"(sg) : "f"(1.0f + eg));
            out[((size_t)(t - 1) * BATCH + b) * NST + i] = oq * oq * sg;
        }

        #pragma unroll
        for (int m = 0; m < 4; m++) { qp[m] = qq[m]; kk[m] = kn[m]; qq[m] = qn[m]; }
        v_i = v_n; a_i = a_n;
    }

    // final output: out(T-1) = S_T . q_{T-1}
    {
        float2 oa = f2mul(s[0], qp[0]);
        float2 ob = f2mul(s[1], qp[1]);
        oa = f2fma(s[2], qp[2], oa);
        ob = f2fma(s[3], qp[3], ob);
        oa = f2add(oa, ob);
        float oq = oa.x + oa.y;
        oq += __shfl_xor_sync(0xffffffffu, oq, 1);
        oq += __shfl_xor_sync(0xffffffffu, oq, 2);
        oq += __shfl_xor_sync(0xffffffffu, oq, 4);
        if (c == 0) {
            float eg;
            asm("ex2.approx.f32 %0, %1;" : "=f"(eg) : "f"(-L2E * oq));
            float sg;
            asm("rcp.approx.f32 %0, %1;" : "=f"(sg) : "f"(1.0f + eg));
            out[((size_t)(T_STEPS - 1) * BATCH + b) * NST + i] = oq * oq * sg;
        }
    }

    // write S_final
    float* fp = &Sfin[(size_t)(b * NST + i) * NST + c * 8];
    reinterpret_cast<float4*>(fp)[0] = make_float4(s[0].x, s[0].y, s[1].x, s[1].y);
    reinterpret_cast<float4*>(fp)[1] = make_float4(s[2].x, s[2].y, s[3].x, s[3].y);
}

// ============================================================================
extern "C" void kernel_launch(void* const* d_in, const int* in_sizes, int n_in,
                              void* d_out, int out_size) {
    const float* x   = (const float*)d_in[0];
    const float* S0  = (const float*)d_in[1];
    const float* Wk  = (const float*)d_in[2];
    const float* Wv  = (const float*)d_in[3];
    const float* Wq  = (const float*)d_in[4];
    const float* Wa  = (const float*)d_in[5];
    const float* ba  = (const float*)d_in[6];
    const float* dg  = (const float*)d_in[7];
    const float* bg  = (const float*)d_in[8];

    float* out  = (float*)d_out;                         // [T,B,N]
    float* Sfin = out + (size_t)T_STEPS * BATCH * NST;   // [B,N,N]

    dim3 g1(M_ROWS / PBM, 2);
    proj_kernel<<<g1, 256>>>(x, Wk, Wq, Wv, Wa, ba);
    scan_kernel<<<128, 32>>>(S0, dg, bg, out, Sfin);
}

// round 5
// speedup vs baseline: 1.3101x; 1.3101x over previous
#include <cuda_runtime.h>
#include <cstdint>
#include <cstring>

#define T_STEPS 2048
#define BATCH   8
#define DIMK    1024
#define NST     64
#define M_ROWS  (T_STEPS * BATCH)
#define NCOL    256

// 16 MB scratch: projections, layout [t*BATCH+b][ k(0:64) | q(64:128) | v(128:192) | alpha(192:256) ]
__device__ __align__(16) float g_proj[(size_t)M_ROWS * NCOL];

union F2U { float2 f2; unsigned long long u; };

__device__ __forceinline__ float2 f2fma(float2 a, float2 b, float2 c) {
    F2U ua, ub, uc, ud; ua.f2 = a; ub.f2 = b; uc.f2 = c;
    asm("fma.rn.f32x2 %0, %1, %2, %3;" : "=l"(ud.u) : "l"(ua.u), "l"(ub.u), "l"(uc.u));
    return ud.f2;
}
__device__ __forceinline__ float2 f2mul(float2 a, float2 b) {
    F2U ua, ub, ud; ua.f2 = a; ub.f2 = b;
    asm("mul.rn.f32x2 %0, %1, %2;" : "=l"(ud.u) : "l"(ua.u), "l"(ub.u));
    return ud.f2;
}
__device__ __forceinline__ float2 f2add(float2 a, float2 b) {
    F2U ua, ub, ud; ua.f2 = a; ub.f2 = b;
    asm("add.rn.f32x2 %0, %1, %2;" : "=l"(ud.u) : "l"(ua.u), "l"(ub.u));
    return ud.f2;
}
__device__ __forceinline__ float2 f2dup(float a) {
    F2U ud;
    asm("mov.b64 %0, {%1, %1};" : "=l"(ud.u) : "f"(a));
    return ud.f2;
}
__device__ __forceinline__ float sigmoidf_fast(float x) {
    return __fdividef(1.0f, 1.0f + __expf(-x));
}

// ============================================================================
// Kernel 1: fused projection GEMM (R3 version, measured 226us).
// C[m][n] = sum_d x[m][d] * W_sel[n][d]; blockIdx.y selects weight matrix.
// ============================================================================
#define BM 128
#define BN 64
#define BK 16

__global__ void __launch_bounds__(256) proj_kernel(
    const float* __restrict__ x,
    const float* __restrict__ Wk, const float* __restrict__ Wq,
    const float* __restrict__ Wv, const float* __restrict__ Wa,
    const float* __restrict__ b_alpha)
{
    __shared__ __align__(16) float As[BK][BM + 4];
    __shared__ __align__(16) float Bs[BK][BN + 4];

    const int tid = threadIdx.x;
    const int m0  = blockIdx.x * BM;
    const int sel = blockIdx.y;
    const float* W = (sel == 0) ? Wk : (sel == 1) ? Wq : (sel == 2) ? Wv : Wa;

    const int ty = tid >> 4;
    const int tx = tid & 15;

    const int lrow = tid >> 2;
    const int lcol = (tid & 3) * 4;

    float2 acc[4][4];
    #pragma unroll
    for (int ip = 0; ip < 4; ip++)
        #pragma unroll
        for (int j = 0; j < 4; j++) acc[ip][j] = make_float2(0.f, 0.f);

    for (int k0 = 0; k0 < DIMK; k0 += BK) {
        #pragma unroll
        for (int half = 0; half < 2; half++) {
            int r = lrow + half * 64;
            float4 v = *reinterpret_cast<const float4*>(&x[(size_t)(m0 + r) * DIMK + k0 + lcol]);
            As[lcol + 0][r] = v.x; As[lcol + 1][r] = v.y;
            As[lcol + 2][r] = v.z; As[lcol + 3][r] = v.w;
        }
        {
            float4 v = *reinterpret_cast<const float4*>(&W[(size_t)lrow * DIMK + k0 + lcol]);
            Bs[lcol + 0][lrow] = v.x; Bs[lcol + 1][lrow] = v.y;
            Bs[lcol + 2][lrow] = v.z; Bs[lcol + 3][lrow] = v.w;
        }
        __syncthreads();
        #pragma unroll
        for (int k = 0; k < BK; k++) {
            float4 a0 = *reinterpret_cast<const float4*>(&As[k][ty * 8]);
            float4 a1 = *reinterpret_cast<const float4*>(&As[k][ty * 8 + 4]);
            float4 bv = *reinterpret_cast<const float4*>(&Bs[k][tx * 4]);
            float2 a2[4] = { make_float2(a0.x, a0.y), make_float2(a0.z, a0.w),
                             make_float2(a1.x, a1.y), make_float2(a1.z, a1.w) };
            float2 bd[4] = { f2dup(bv.x), f2dup(bv.y), f2dup(bv.z), f2dup(bv.w) };
            #pragma unroll
            for (int ip = 0; ip < 4; ip++)
                #pragma unroll
                for (int j = 0; j < 4; j++)
                    acc[ip][j] = f2fma(a2[ip], bd[j], acc[ip][j]);
        }
        __syncthreads();
    }

    #pragma unroll
    for (int ip = 0; ip < 4; ip++) {
        #pragma unroll
        for (int h = 0; h < 2; h++) {
            int r = ty * 8 + ip * 2 + h;
            float4 o;
            o.x = h ? acc[ip][0].y : acc[ip][0].x;
            o.y = h ? acc[ip][1].y : acc[ip][1].x;
            o.z = h ? acc[ip][2].y : acc[ip][2].x;
            o.w = h ? acc[ip][3].y : acc[ip][3].x;
            if (sel == 3) {
                o.x = sigmoidf_fast(o.x + b_alpha[tx * 4 + 0]);
                o.y = sigmoidf_fast(o.y + b_alpha[tx * 4 + 1]);
                o.z = sigmoidf_fast(o.z + b_alpha[tx * 4 + 2]);
                o.w = sigmoidf_fast(o.w + b_alpha[tx * 4 + 3]);
            }
            *reinterpret_cast<float4*>(&g_proj[(size_t)(m0 + r) * NCOL + sel * 64 + tx * 4]) = o;
        }
    }
}

// ============================================================================
// Kernel 2: sequential scan with decoupled retrieved-value recurrence.
//   r_{t+1} = alpha_t*(s_t . k_{t+1}) + beta_t*(k_t . k_{t+1})
// so the dot+shfl chain runs concurrently with the sigmoid; only a scalar
// FMA -> sigmoid -> beta remains on the tight carried path.
// 128 blocks x 32 threads; 4 rows/warp, 8 lanes/row. Loop unrolled x2 with
// swapped register banks (rotation-free). Raw outputs; gate applied later.
// ============================================================================
#define DPF 8   // ring slots

struct ScanCtx {
    const float* gp_base;   // &g_proj[b*NCOL]
    float* out;
    uint32_t sbase;
    int b, i, c, loff;
    float dgl, bgl;
};

__device__ __forceinline__ void scan_step(
    const ScanCtx& ctx, int t,
    float2 (&s)[4],
    float2 (&kc)[4], float2 (&kn)[4],    // k_t (in) / k_{t+1} (written)
    float2 (&qp)[4], float2 (&qc)[4],    // q_{t-1} (in) / q_t (written)
    float v_c, float a_c,                // v_t, alpha_t (in)
    float& v_n, float& a_n,              // v_{t+1}, alpha_{t+1} (written)
    float& r,                            // r_t in -> r_{t+1} out
    float (&buf)[DPF][NCOL])
{
    // prefetch slot for step t+DPF-1
    {
        int tf = t + DPF - 1;
        if (tf > T_STEPS - 1) tf = T_STEPS - 1;
        int slot = tf & (DPF - 1);
        const float* src = ctx.gp_base + (size_t)tf * BATCH * NCOL + ctx.loff;
        uint32_t sa = ctx.sbase + (uint32_t)(slot * NCOL + ctx.loff) * 4u;
        asm volatile(
            "cp.async.ca.shared.global [%0], [%1], 16;\n\t"
            "cp.async.ca.shared.global [%2], [%3], 16;\n\t"
            :: "r"(sa), "l"(src), "r"(sa + 16u), "l"(src + 4));
        asm volatile("cp.async.commit_group;");
    }
    asm volatile("cp.async.wait_group %0;" :: "n"(DPF - 2));
    __syncwarp();

    // load k_{t+1}, v_{t+1}, alpha_{t+1} (slot t+1) and q_t (slot t)
    const int tn = (t + 1 < T_STEPS) ? (t + 1) : t;
    const float* pn = &buf[tn & (DPF - 1)][0];
    const float* pc = &buf[t & (DPF - 1)][0];
    {
        float4 kv0 = *reinterpret_cast<const float4*>(pn + ctx.c * 8);
        float4 kv1 = *reinterpret_cast<const float4*>(pn + ctx.c * 8 + 4);
        kn[0] = make_float2(kv0.x, kv0.y); kn[1] = make_float2(kv0.z, kv0.w);
        kn[2] = make_float2(kv1.x, kv1.y); kn[3] = make_float2(kv1.z, kv1.w);
        float4 qv0 = *reinterpret_cast<const float4*>(pc + 64 + ctx.c * 8);
        float4 qv1 = *reinterpret_cast<const float4*>(pc + 64 + ctx.c * 8 + 4);
        qc[0] = make_float2(qv0.x, qv0.y); qc[1] = make_float2(qv0.z, qv0.w);
        qc[2] = make_float2(qv1.x, qv1.y); qc[3] = make_float2(qv1.z, qv1.w);
        v_n = pn[128 + ctx.i];
        a_n = pn[192 + ctx.i];
    }

    // three dots, none on the sigmoid path:
    //   a1 = s . k_{t+1},  oq = s . q_{t-1} (= out_{t-1}),  d2 = k_t . k_{t+1}
    float2 xa = f2mul(s[0], kn[0]);
    float2 xb = f2mul(s[1], kn[1]);
    float2 oa = f2mul(s[0], qp[0]);
    float2 ob = f2mul(s[1], qp[1]);
    float2 da = f2mul(kc[0], kn[0]);
    float2 db = f2mul(kc[1], kn[1]);
    xa = f2fma(s[2], kn[2], xa);
    xb = f2fma(s[3], kn[3], xb);
    oa = f2fma(s[2], qp[2], oa);
    ob = f2fma(s[3], qp[3], ob);
    da = f2fma(kc[2], kn[2], da);
    db = f2fma(kc[3], kn[3], db);
    xa = f2add(xa, xb);
    oa = f2add(oa, ob);
    da = f2add(da, db);
    float a1 = xa.x + xa.y;
    float oq = oa.x + oa.y;
    float d2 = da.x + da.y;

    a1 += __shfl_xor_sync(0xffffffffu, a1, 1);
    oq += __shfl_xor_sync(0xffffffffu, oq, 1);
    d2 += __shfl_xor_sync(0xffffffffu, d2, 1);
    a1 += __shfl_xor_sync(0xffffffffu, a1, 2);
    oq += __shfl_xor_sync(0xffffffffu, oq, 2);
    d2 += __shfl_xor_sync(0xffffffffu, d2, 2);
    a1 += __shfl_xor_sync(0xffffffffu, a1, 4);
    oq += __shfl_xor_sync(0xffffffffu, oq, 4);
    d2 += __shfl_xor_sync(0xffffffffu, d2, 4);

    // g_t = sigmoid(d*r_t + b); depends only on carried scalar r
    float e;
    asm("ex2.approx.f32 %0, %1;" : "=f"(e) : "f"(__fmaf_rn(ctx.dgl, r, ctx.bgl)));
    float gt;
    asm("rcp.approx.f32 %0, %1;" : "=f"(gt) : "f"(1.0f + e));
    const float beta = (1.0f - a_c) * v_c * gt;

    // state update s = alpha*s + beta*k_t
    const float2 av = f2dup(a_c);
    const float2 bv = f2dup(beta);
    #pragma unroll
    for (int m = 0; m < 4; m++)
        s[m] = f2fma(av, s[m], f2mul(bv, kc[m]));

    // r_{t+1} = alpha*a1 + beta*d2
    r = __fmaf_rn(a_c, a1, beta * d2);

    // store out_{t-1} (raw)
    if (t > 0 && ctx.c == 0)
        ctx.out[((size_t)(t - 1) * BATCH + ctx.b) * NST + ctx.i] = oq;
}

__global__ void __launch_bounds__(32) scan_kernel(
    const float* __restrict__ S0,
    const float* __restrict__ d_g,
    const float* __restrict__ b_g,
    float* __restrict__ out,     // [T,B,N] raw
    float* __restrict__ Sfin)    // [B,N,N]
{
    __shared__ __align__(16) float buf[DPF][NCOL];

    const int bx   = blockIdx.x;
    const int b    = bx >> 4;
    const int rg   = bx & 15;
    const int lane = threadIdx.x;
    const int r_   = lane >> 3;
    const int c    = lane & 7;
    const int i    = rg * 4 + r_;

    const float L2E = 1.4426950408889634f;

    ScanCtx ctx;
    ctx.gp_base = &g_proj[(size_t)b * NCOL];
    ctx.out  = out;
    ctx.b = b; ctx.i = i; ctx.c = c;
    ctx.loff = lane * 8;
    ctx.dgl = -d_g[i] * L2E;
    ctx.bgl = -b_g[i] * L2E;
    ctx.sbase = (uint32_t)__cvta_generic_to_shared(&buf[0][0]);

    float2 s[4];
    {
        const float4* sp = reinterpret_cast<const float4*>(&S0[(size_t)(b * NST + i) * NST + c * 8]);
        float4 v0 = sp[0], v1 = sp[1];
        s[0] = make_float2(v0.x, v0.y); s[1] = make_float2(v0.z, v0.w);
        s[2] = make_float2(v1.x, v1.y); s[3] = make_float2(v1.z, v1.w);
    }

    // prologue: fill ring slots 0..DPF-2
    #pragma unroll
    for (int d = 0; d < DPF - 1; d++) {
        const float* src = ctx.gp_base + (size_t)d * BATCH * NCOL + ctx.loff;
        uint32_t sa = ctx.sbase + (uint32_t)(d * NCOL + ctx.loff) * 4u;
        asm volatile(
            "cp.async.ca.shared.global [%0], [%1], 16;\n\t"
            "cp.async.ca.shared.global [%2], [%3], 16;\n\t"
            :: "r"(sa), "l"(src), "r"(sa + 16u), "l"(src + 4));
        asm volatile("cp.async.commit_group;");
    }
    asm volatile("cp.async.wait_group %0;" :: "n"(DPF - 2));
    __syncwarp();

    // load step-0 operands: kA = k_0, v/a_0; qA = q_{-1} = 0
    float2 kA[4], kB[4], qA[4], qB[4];
    float vA, aA, vB, aB;
    {
        const float* p = &buf[0][0];
        float4 kv0 = *reinterpret_cast<const float4*>(p + c * 8);
        float4 kv1 = *reinterpret_cast<const float4*>(p + c * 8 + 4);
        kA[0] = make_float2(kv0.x, kv0.y); kA[1] = make_float2(kv0.z, kv0.w);
        kA[2] = make_float2(kv1.x, kv1.y); kA[3] = make_float2(kv1.z, kv1.w);
        vA = p[128 + i];
        aA = p[192 + i];
    }
    #pragma unroll
    for (int m = 0; m < 4; m++) { qA[m] = make_float2(0.f, 0.f); }

    // r_0 = s_0 . k_0
    float r;
    {
        float2 ra = f2mul(s[0], kA[0]);
        float2 rb = f2mul(s[1], kA[1]);
        ra = f2fma(s[2], kA[2], ra);
        rb = f2fma(s[3], kA[3], rb);
        ra = f2add(ra, rb);
        r = ra.x + ra.y;
        r += __shfl_xor_sync(0xffffffffu, r, 1);
        r += __shfl_xor_sync(0xffffffffu, r, 2);
        r += __shfl_xor_sync(0xffffffffu, r, 4);
    }

    // main loop, unrolled x2 with swapped register banks
    for (int t = 0; t < T_STEPS; t += 2) {
        scan_step(ctx, t,     s, kA, kB, qA, qB, vA, aA, vB, aB, r, buf);
        scan_step(ctx, t + 1, s, kB, kA, qB, qA, vB, aB, vA, aA, r, buf);
    }

    // out_{T-1} = s_T . q_{T-1}; q_{T-1} lives in bank qA (written at t=2047)
    {
        float2 oa = f2mul(s[0], qA[0]);
        float2 ob = f2mul(s[1], qA[1]);
        oa = f2fma(s[2], qA[2], oa);
        ob = f2fma(s[3], qA[3], ob);
        oa = f2add(oa, ob);
        float oq = oa.x + oa.y;
        oq += __shfl_xor_sync(0xffffffffu, oq, 1);
        oq += __shfl_xor_sync(0xffffffffu, oq, 2);
        oq += __shfl_xor_sync(0xffffffffu, oq, 4);
        if (c == 0)
            out[((size_t)(T_STEPS - 1) * BATCH + b) * NST + i] = oq;
    }

    // write S_final
    float* fp = &Sfin[(size_t)(b * NST + i) * NST + c * 8];
    reinterpret_cast<float4*>(fp)[0] = make_float4(s[0].x, s[0].y, s[1].x, s[1].y);
    reinterpret_cast<float4*>(fp)[1] = make_float4(s[2].x, s[2].y, s[3].x, s[3].y);
}

// ============================================================================
// Kernel 3: apply self-gate y = x * silu(x) = x^2 * sigmoid(x) over out[T,B,N]
// ============================================================================
__global__ void __launch_bounds__(256) gate_kernel(float* __restrict__ out)
{
    int idx = blockIdx.x * 1024 + threadIdx.x * 4;
    float4 v = *reinterpret_cast<float4*>(&out[idx]);
    v.x = v.x * v.x * sigmoidf_fast(v.x);
    v.y = v.y * v.y * sigmoidf_fast(v.y);
    v.z = v.z * v.z * sigmoidf_fast(v.z);
    v.w = v.w * v.w * sigmoidf_fast(v.w);
    *reinterpret_cast<float4*>(&out[idx]) = v;
}

// ============================================================================
extern "C" void kernel_launch(void* const* d_in, const int* in_sizes, int n_in,
                              void* d_out, int out_size) {
    const float* x   = (const float*)d_in[0];
    const float* S0  = (const float*)d_in[1];
    const float* Wk  = (const float*)d_in[2];
    const float* Wv  = (const float*)d_in[3];
    const float* Wq  = (const float*)d_in[4];
    const float* Wa  = (const float*)d_in[5];
    const float* ba  = (const float*)d_in[6];
    const float* dg  = (const float*)d_in[7];
    const float* bg  = (const float*)d_in[8];

    float* out  = (float*)d_out;                         // [T,B,N]
    float* Sfin = out + (size_t)T_STEPS * BATCH * NST;   // [B,N,N]

    dim3 g1(M_ROWS / BM, 4);
    proj_kernel<<<g1, 256>>>(x, Wk, Wq, Wv, Wa, ba);
    scan_kernel<<<128, 32>>>(S0, dg, bg, out, Sfin);
    gate_kernel<<<(T_STEPS * BATCH * NST) / 1024, 256>>>(out);
}

// round 6
// speedup vs baseline: 1.3297x; 1.0149x over previous
#include <cuda_runtime.h>
#include <cstdint>
#include <cstring>

#define T_STEPS 2048
#define BATCH   8
#define DIMK    1024
#define NST     64
#define M_ROWS  (T_STEPS * BATCH)
#define NCOL    256

// 16 MB scratch: projections, layout [t*BATCH+b][ k(0:64) | q(64:128) | v(128:192) | alpha(192:256) ]
__device__ __align__(16) float g_proj[(size_t)M_ROWS * NCOL];

union F2U { float2 f2; unsigned long long u; };

__device__ __forceinline__ float2 f2fma(float2 a, float2 b, float2 c) {
    F2U ua, ub, uc, ud; ua.f2 = a; ub.f2 = b; uc.f2 = c;
    asm("fma.rn.f32x2 %0, %1, %2, %3;" : "=l"(ud.u) : "l"(ua.u), "l"(ub.u), "l"(uc.u));
    return ud.f2;
}
__device__ __forceinline__ float2 f2mul(float2 a, float2 b) {
    F2U ua, ub, ud; ua.f2 = a; ub.f2 = b;
    asm("mul.rn.f32x2 %0, %1, %2;" : "=l"(ud.u) : "l"(ua.u), "l"(ub.u));
    return ud.f2;
}
__device__ __forceinline__ float2 f2add(float2 a, float2 b) {
    F2U ua, ub, ud; ua.f2 = a; ub.f2 = b;
    asm("add.rn.f32x2 %0, %1, %2;" : "=l"(ud.u) : "l"(ua.u), "l"(ub.u));
    return ud.f2;
}
__device__ __forceinline__ float2 f2dup(float a) {
    F2U ud;
    asm("mov.b64 %0, {%1, %1};" : "=l"(ud.u) : "f"(a));
    return ud.f2;
}
__device__ __forceinline__ float sigmoidf_fast(float x) {
    return __fdividef(1.0f, 1.0f + __expf(-x));
}

// ============================================================================
// Kernel 1: projection GEMM v3 — wavefront-optimal 8x8 microtile.
// BM=128, BN=64, BK=16, 128 threads (4 warps). Warp = 64m x 32n; lanes 8(m)x4(n).
// Thread rows: lane_m*4 + {0..3} and +32 -> every LDS.128 is 1 wavefront.
// Double-buffered smem, one __syncthreads per K-tile, register-prefetched LDG.
// ============================================================================
#define BM 128
#define BN 64
#define BK 16
#define ASTRIDE (BM + 4)   // 132 floats, 16B-aligned rows
#define BSTRIDE (BN + 4)   // 68

__global__ void __launch_bounds__(128, 4) proj_kernel(
    const float* __restrict__ x,
    const float* __restrict__ Wk, const float* __restrict__ Wq,
    const float* __restrict__ Wv, const float* __restrict__ Wa,
    const float* __restrict__ b_alpha)
{
    __shared__ __align__(16) float As[2][BK][ASTRIDE];
    __shared__ __align__(16) float Bs[2][BK][BSTRIDE];

    const int tid = threadIdx.x;
    const int m0  = blockIdx.x * BM;
    const int sel = blockIdx.y;
    const float* W = (sel == 0) ? Wk : (sel == 1) ? Wq : (sel == 2) ? Wv : Wa;

    const int warp  = tid >> 5;
    const int lane  = tid & 31;
    const int wm    = warp >> 1;          // 0..1
    const int wn    = warp & 1;           // 0..1
    const int lane_m = lane & 7;          // 0..7
    const int lane_n = lane >> 3;         // 0..3
    const int arow  = wm * 64 + lane_m * 4;      // rows arow..+3 and arow+32..+35
    const int bcol  = wn * 32 + lane_n * 8;      // cols bcol..+7

    // coalesced loaders
    const int xrow = tid >> 2;            // 0..31
    const int xcol = (tid & 3) * 4;       // 0,4,8,12
    const int wrow = tid >> 1;            // 0..63
    const int wcol = (tid & 1) * 8;       // 0 or 8

    const float* xp = &x[(size_t)(m0 + xrow) * DIMK + xcol];
    const float* wp = &W[(size_t)wrow * DIMK + wcol];

    float4 xr[4], wr[2];
    #pragma unroll
    for (int j = 0; j < 4; j++)
        xr[j] = *reinterpret_cast<const float4*>(xp + (size_t)j * 32 * DIMK);
    wr[0] = *reinterpret_cast<const float4*>(wp);
    wr[1] = *reinterpret_cast<const float4*>(wp + 4);

    float2 acc[4][8];
    #pragma unroll
    for (int ip = 0; ip < 4; ip++)
        #pragma unroll
        for (int j = 0; j < 8; j++) acc[ip][j] = make_float2(0.f, 0.f);

    int p = 0;
    for (int k0 = 0; k0 < DIMK; k0 += BK) {
        // stage registers -> smem (transposed)
        #pragma unroll
        for (int j = 0; j < 4; j++) {
            const int r = xrow + j * 32;
            As[p][xcol + 0][r] = xr[j].x;
            As[p][xcol + 1][r] = xr[j].y;
            As[p][xcol + 2][r] = xr[j].z;
            As[p][xcol + 3][r] = xr[j].w;
        }
        Bs[p][wcol + 0][wrow] = wr[0].x;
        Bs[p][wcol + 1][wrow] = wr[0].y;
        Bs[p][wcol + 2][wrow] = wr[0].z;
        Bs[p][wcol + 3][wrow] = wr[0].w;
        Bs[p][wcol + 4][wrow] = wr[1].x;
        Bs[p][wcol + 5][wrow] = wr[1].y;
        Bs[p][wcol + 6][wrow] = wr[1].z;
        Bs[p][wcol + 7][wrow] = wr[1].w;
        __syncthreads();

        // prefetch next K-tile
        if (k0 + BK < DIMK) {
            #pragma unroll
            for (int j = 0; j < 4; j++)
                xr[j] = *reinterpret_cast<const float4*>(xp + (size_t)j * 32 * DIMK + k0 + BK);
            wr[0] = *reinterpret_cast<const float4*>(wp + k0 + BK);
            wr[1] = *reinterpret_cast<const float4*>(wp + k0 + BK + 4);
        }

        #pragma unroll
        for (int k = 0; k < BK; k++) {
            float4 a0 = *reinterpret_cast<const float4*>(&As[p][k][arow]);
            float4 a1 = *reinterpret_cast<const float4*>(&As[p][k][arow + 32]);
            float2 am[4] = { make_float2(a0.x, a0.y), make_float2(a0.z, a0.w),
                             make_float2(a1.x, a1.y), make_float2(a1.z, a1.w) };
            {
                float4 b0 = *reinterpret_cast<const float4*>(&Bs[p][k][bcol]);
                float2 bd[4] = { f2dup(b0.x), f2dup(b0.y), f2dup(b0.z), f2dup(b0.w) };
                #pragma unroll
                for (int ip = 0; ip < 4; ip++)
                    #pragma unroll
                    for (int j = 0; j < 4; j++)
                        acc[ip][j] = f2fma(am[ip], bd[j], acc[ip][j]);
            }
            {
                float4 b1 = *reinterpret_cast<const float4*>(&Bs[p][k][bcol + 4]);
                float2 bd[4] = { f2dup(b1.x), f2dup(b1.y), f2dup(b1.z), f2dup(b1.w) };
                #pragma unroll
                for (int ip = 0; ip < 4; ip++)
                    #pragma unroll
                    for (int j = 0; j < 4; j++)
                        acc[ip][j + 4] = f2fma(am[ip], bd[j], acc[ip][j + 4]);
            }
        }
        p ^= 1;
    }

    // epilogue: row(ip,h) = m0 + arow + (ip>>1)*32 + (ip&1)*2 + h; cols bcol..+7
    #pragma unroll
    for (int ip = 0; ip < 4; ip++) {
        #pragma unroll
        for (int h = 0; h < 2; h++) {
            const int row = m0 + arow + (ip >> 1) * 32 + (ip & 1) * 2 + h;
            float o[8];
            #pragma unroll
            for (int j = 0; j < 8; j++)
                o[j] = h ? acc[ip][j].y : acc[ip][j].x;
            if (sel == 3) {
                #pragma unroll
                for (int j = 0; j < 8; j++)
                    o[j] = sigmoidf_fast(o[j] + b_alpha[bcol + j]);
            }
            float* dst = &g_proj[(size_t)row * NCOL + sel * 64 + bcol];
            *reinterpret_cast<float4*>(dst)     = make_float4(o[0], o[1], o[2], o[3]);
            *reinterpret_cast<float4*>(dst + 4) = make_float4(o[4], o[5], o[6], o[7]);
        }
    }
}

// ============================================================================
// Kernel 2: sequential scan with decoupled retrieved-value recurrence (R5).
//   r_{t+1} = alpha_t*(s_t . k_{t+1}) + beta_t*(k_t . k_{t+1})
// 128 blocks x 32 threads; 4 rows/warp, 8 lanes/row. Unrolled x2, swapped banks.
// ============================================================================
#define DPF 8   // ring slots

struct ScanCtx {
    const float* gp_base;   // &g_proj[b*NCOL]
    float* out;
    uint32_t sbase;
    int b, i, c, loff;
    float dgl, bgl;
};

__device__ __forceinline__ void scan_step(
    const ScanCtx& ctx, int t,
    float2 (&s)[4],
    float2 (&kc)[4], float2 (&kn)[4],    // k_t (in) / k_{t+1} (written)
    float2 (&qp)[4], float2 (&qc)[4],    // q_{t-1} (in) / q_t (written)
    float v_c, float a_c,                // v_t, alpha_t (in)
    float& v_n, float& a_n,              // v_{t+1}, alpha_{t+1} (written)
    float& r,                            // r_t in -> r_{t+1} out
    float (&buf)[DPF][NCOL])
{
    // prefetch slot for step t+DPF-1
    {
        int tf = t + DPF - 1;
        if (tf > T_STEPS - 1) tf = T_STEPS - 1;
        int slot = tf & (DPF - 1);
        const float* src = ctx.gp_base + (size_t)tf * BATCH * NCOL + ctx.loff;
        uint32_t sa = ctx.sbase + (uint32_t)(slot * NCOL + ctx.loff) * 4u;
        asm volatile(
            "cp.async.ca.shared.global [%0], [%1], 16;\n\t"
            "cp.async.ca.shared.global [%2], [%3], 16;\n\t"
            :: "r"(sa), "l"(src), "r"(sa + 16u), "l"(src + 4));
        asm volatile("cp.async.commit_group;");
    }
    asm volatile("cp.async.wait_group %0;" :: "n"(DPF - 2));
    __syncwarp();

    // load k_{t+1}, v_{t+1}, alpha_{t+1} (slot t+1) and q_t (slot t)
    const int tn = (t + 1 < T_STEPS) ? (t + 1) : t;
    const float* pn = &buf[tn & (DPF - 1)][0];
    const float* pc = &buf[t & (DPF - 1)][0];
    {
        float4 kv0 = *reinterpret_cast<const float4*>(pn + ctx.c * 8);
        float4 kv1 = *reinterpret_cast<const float4*>(pn + ctx.c * 8 + 4);
        kn[0] = make_float2(kv0.x, kv0.y); kn[1] = make_float2(kv0.z, kv0.w);
        kn[2] = make_float2(kv1.x, kv1.y); kn[3] = make_float2(kv1.z, kv1.w);
        float4 qv0 = *reinterpret_cast<const float4*>(pc + 64 + ctx.c * 8);
        float4 qv1 = *reinterpret_cast<const float4*>(pc + 64 + ctx.c * 8 + 4);
        qc[0] = make_float2(qv0.x, qv0.y); qc[1] = make_float2(qv0.z, qv0.w);
        qc[2] = make_float2(qv1.x, qv1.y); qc[3] = make_float2(qv1.z, qv1.w);
        v_n = pn[128 + ctx.i];
        a_n = pn[192 + ctx.i];
    }

    // three dots, none on the sigmoid path:
    //   a1 = s . k_{t+1},  oq = s . q_{t-1} (= out_{t-1}),  d2 = k_t . k_{t+1}
    float2 xa = f2mul(s[0], kn[0]);
    float2 xb = f2mul(s[1], kn[1]);
    float2 oa = f2mul(s[0], qp[0]);
    float2 ob = f2mul(s[1], qp[1]);
    float2 da = f2mul(kc[0], kn[0]);
    float2 db = f2mul(kc[1], kn[1]);
    xa = f2fma(s[2], kn[2], xa);
    xb = f2fma(s[3], kn[3], xb);
    oa = f2fma(s[2], qp[2], oa);
    ob = f2fma(s[3], qp[3], ob);
    da = f2fma(kc[2], kn[2], da);
    db = f2fma(kc[3], kn[3], db);
    xa = f2add(xa, xb);
    oa = f2add(oa, ob);
    da = f2add(da, db);
    float a1 = xa.x + xa.y;
    float oq = oa.x + oa.y;
    float d2 = da.x + da.y;

    a1 += __shfl_xor_sync(0xffffffffu, a1, 1);
    oq += __shfl_xor_sync(0xffffffffu, oq, 1);
    d2 += __shfl_xor_sync(0xffffffffu, d2, 1);
    a1 += __shfl_xor_sync(0xffffffffu, a1, 2);
    oq += __shfl_xor_sync(0xffffffffu, oq, 2);
    d2 += __shfl_xor_sync(0xffffffffu, d2, 2);
    a1 += __shfl_xor_sync(0xffffffffu, a1, 4);
    oq += __shfl_xor_sync(0xffffffffu, oq, 4);
    d2 += __shfl_xor_sync(0xffffffffu, d2, 4);

    // g_t = sigmoid(d*r_t + b); depends only on carried scalar r
    float e;
    asm("ex2.approx.f32 %0, %1;" : "=f"(e) : "f"(__fmaf_rn(ctx.dgl, r, ctx.bgl)));
    float gt;
    asm("rcp.approx.f32 %0, %1;" : "=f"(gt) : "f"(1.0f + e));
    const float beta = (1.0f - a_c) * v_c * gt;

    // state update s = alpha*s + beta*k_t
    const float2 av = f2dup(a_c);
    const float2 bv = f2dup(beta);
    #pragma unroll
    for (int m = 0; m < 4; m++)
        s[m] = f2fma(av, s[m], f2mul(bv, kc[m]));

    // r_{t+1} = alpha*a1 + beta*d2
    r = __fmaf_rn(a_c, a1, beta * d2);

    // store out_{t-1} (raw)
    if (t > 0 && ctx.c == 0)
        ctx.out[((size_t)(t - 1) * BATCH + ctx.b) * NST + ctx.i] = oq;
}

__global__ void __launch_bounds__(32) scan_kernel(
    const float* __restrict__ S0,
    const float* __restrict__ d_g,
    const float* __restrict__ b_g,
    float* __restrict__ out,     // [T,B,N] raw
    float* __restrict__ Sfin)    // [B,N,N]
{
    __shared__ __align__(16) float buf[DPF][NCOL];

    const int bx   = blockIdx.x;
    const int b    = bx >> 4;
    const int rg   = bx & 15;
    const int lane = threadIdx.x;
    const int r_   = lane >> 3;
    const int c    = lane & 7;
    const int i    = rg * 4 + r_;

    const float L2E = 1.4426950408889634f;

    ScanCtx ctx;
    ctx.gp_base = &g_proj[(size_t)b * NCOL];
    ctx.out  = out;
    ctx.b = b; ctx.i = i; ctx.c = c;
    ctx.loff = lane * 8;
    ctx.dgl = -d_g[i] * L2E;
    ctx.bgl = -b_g[i] * L2E;
    ctx.sbase = (uint32_t)__cvta_generic_to_shared(&buf[0][0]);

    float2 s[4];
    {
        const float4* sp = reinterpret_cast<const float4*>(&S0[(size_t)(b * NST + i) * NST + c * 8]);
        float4 v0 = sp[0], v1 = sp[1];
        s[0] = make_float2(v0.x, v0.y); s[1] = make_float2(v0.z, v0.w);
        s[2] = make_float2(v1.x, v1.y); s[3] = make_float2(v1.z, v1.w);
    }

    // prologue: fill ring slots 0..DPF-2
    #pragma unroll
    for (int d = 0; d < DPF - 1; d++) {
        const float* src = ctx.gp_base + (size_t)d * BATCH * NCOL + ctx.loff;
        uint32_t sa = ctx.sbase + (uint32_t)(d * NCOL + ctx.loff) * 4u;
        asm volatile(
            "cp.async.ca.shared.global [%0], [%1], 16;\n\t"
            "cp.async.ca.shared.global [%2], [%3], 16;\n\t"
            :: "r"(sa), "l"(src), "r"(sa + 16u), "l"(src + 4));
        asm volatile("cp.async.commit_group;");
    }
    asm volatile("cp.async.wait_group %0;" :: "n"(DPF - 2));
    __syncwarp();

    // load step-0 operands: kA = k_0, v/a_0; qA = q_{-1} = 0
    float2 kA[4], kB[4], qA[4], qB[4];
    float vA, aA, vB, aB;
    {
        const float* p = &buf[0][0];
        float4 kv0 = *reinterpret_cast<const float4*>(p + c * 8);
        float4 kv1 = *reinterpret_cast<const float4*>(p + c * 8 + 4);
        kA[0] = make_float2(kv0.x, kv0.y); kA[1] = make_float2(kv0.z, kv0.w);
        kA[2] = make_float2(kv1.x, kv1.y); kA[3] = make_float2(kv1.z, kv1.w);
        vA = p[128 + i];
        aA = p[192 + i];
    }
    #pragma unroll
    for (int m = 0; m < 4; m++) { qA[m] = make_float2(0.f, 0.f); }

    // r_0 = s_0 . k_0
    float r;
    {
        float2 ra = f2mul(s[0], kA[0]);
        float2 rb = f2mul(s[1], kA[1]);
        ra = f2fma(s[2], kA[2], ra);
        rb = f2fma(s[3], kA[3], rb);
        ra = f2add(ra, rb);
        r = ra.x + ra.y;
        r += __shfl_xor_sync(0xffffffffu, r, 1);
        r += __shfl_xor_sync(0xffffffffu, r, 2);
        r += __shfl_xor_sync(0xffffffffu, r, 4);
    }

    // main loop, unrolled x2 with swapped register banks
    for (int t = 0; t < T_STEPS; t += 2) {
        scan_step(ctx, t,     s, kA, kB, qA, qB, vA, aA, vB, aB, r, buf);
        scan_step(ctx, t + 1, s, kB, kA, qB, qA, vB, aB, vA, aA, r, buf);
    }

    // out_{T-1} = s_T . q_{T-1}; q_{T-1} lives in bank qA (written at t=2047)
    {
        float2 oa = f2mul(s[0], qA[0]);
        float2 ob = f2mul(s[1], qA[1]);
        oa = f2fma(s[2], qA[2], oa);
        ob = f2fma(s[3], qA[3], ob);
        oa = f2add(oa, ob);
        float oq = oa.x + oa.y;
        oq += __shfl_xor_sync(0xffffffffu, oq, 1);
        oq += __shfl_xor_sync(0xffffffffu, oq, 2);
        oq += __shfl_xor_sync(0xffffffffu, oq, 4);
        if (c == 0)
            out[((size_t)(T_STEPS - 1) * BATCH + b) * NST + i] = oq;
    }

    // write S_final
    float* fp = &Sfin[(size_t)(b * NST + i) * NST + c * 8];
    reinterpret_cast<float4*>(fp)[0] = make_float4(s[0].x, s[0].y, s[1].x, s[1].y);
    reinterpret_cast<float4*>(fp)[1] = make_float4(s[2].x, s[2].y, s[3].x, s[3].y);
}

// ============================================================================
// Kernel 3: apply self-gate y = x * silu(x) = x^2 * sigmoid(x) over out[T,B,N]
// ============================================================================
__global__ void __launch_bounds__(256) gate_kernel(float* __restrict__ out)
{
    int idx = blockIdx.x * 1024 + threadIdx.x * 4;
    float4 v = *reinterpret_cast<float4*>(&out[idx]);
    v.x = v.x * v.x * sigmoidf_fast(v.x);
    v.y = v.y * v.y * sigmoidf_fast(v.y);
    v.z = v.z * v.z * sigmoidf_fast(v.z);
    v.w = v.w * v.w * sigmoidf_fast(v.w);
    *reinterpret_cast<float4*>(&out[idx]) = v;
}

// ============================================================================
extern "C" void kernel_launch(void* const* d_in, const int* in_sizes, int n_in,
                              void* d_out, int out_size) {
    const float* x   = (const float*)d_in[0];
    const float* S0  = (const float*)d_in[1];
    const float* Wk  = (const float*)d_in[2];
    const float* Wv  = (const float*)d_in[3];
    const float* Wq  = (const float*)d_in[4];
    const float* Wa  = (const float*)d_in[5];
    const float* ba  = (const float*)d_in[6];
    const float* dg  = (const float*)d_in[7];
    const float* bg  = (const float*)d_in[8];

    float* out  = (float*)d_out;                         // [T,B,N]
    float* Sfin = out + (size_t)T_STEPS * BATCH * NST;   // [B,N,N]

    dim3 g1(M_ROWS / BM, 4);
    proj_kernel<<<g1, 128>>>(x, Wk, Wq, Wv, Wa, ba);
    scan_kernel<<<128, 32>>>(S0, dg, bg, out, Sfin);
    gate_kernel<<<(T_STEPS * BATCH * NST) / 1024, 256>>>(out);
}